// round 11
// baseline (speedup 1.0000x reference)
#include <cuda_runtime.h>

#define Wn 262144
#define Ln 32
#define Nn (Ln * Wn)
#define CAP 2048   // spawned-sibling queue (nonterminals only); expected ~16 total

// Linear DAG cone evaluation, single warp, software-pipelined pointer chase.
// root = sum over path-tree leaves of (prod path weights) * values[leaf] * w_term.
// The next hop's dependent gather is issued BEFORE the warp bookkeeping
// (ballots/queue/claims), hiding that overhead under the load latency.
__global__ void __launch_bounds__(32) cone_kernel(
    const float* __restrict__ values,
    const int2*  __restrict__ idx2,     // child_idx as [L-1,W] int2
    const int*   __restrict__ types,    // node_types [L-1,W]
    const float* __restrict__ w_term,
    const float* __restrict__ w_plus,
    const float* __restrict__ w_minus,
    const float* __restrict__ w_final,
    const float* __restrict__ b_final,
    float* __restrict__ out)
{
    __shared__ int2 s_q[CAP];           // (node id, coef bits)

    const int lane = threadIdx.x;
    const unsigned below = (1u << lane) - 1u;
    const unsigned FULL = 0xFFFFFFFFu;
    const float2 P = *(const float2*)w_plus;
    const float2 M = *(const float2*)w_minus;

    float acc = 0.0f;
    int head = 0, tail = 0;             // warp-uniform cursors, no atomics

    bool  active = (lane == 0);
    float c = 1.0f;
    int2  ch;                           // pre-issued gather result for current node
    int   t;

    if (active) {                       // prologue: issue root's gather
        ch = __ldg(&idx2[(Nn - 1) - Wn]);
        t  = __ldg(&types[(Nn - 1) - Wn]);
    }

    for (int iter = 0; iter < 96; iter++) {
        bool spawn = false;
        int   sv = 0;
        float sc = 0.0f;

        if (active) {
            // consume the pre-issued gather
            float c0 = c * ((t == 1) ? P.x : M.x);
            float c1 = c * ((t == 1) ? P.y : M.y);

            bool xt = (ch.x < Wn), yt = (ch.y < Wn);
            if (xt) acc += c0 * __ldg(&values[ch.x]);   // terminal inline
            if (yt) acc += c1 * __ldg(&values[ch.y]);

            int v = 0;
            if (!xt) {                           // follow x in registers
                v = ch.x; c = c0;
                if (!yt) { spawn = true; sv = ch.y; sc = c1; }
            } else if (!yt) {                    // follow y in registers
                v = ch.y; c = c1;
            } else {
                active = false;                  // both terminal: lane done
            }
            if (active) {
                // ISSUE NEXT HOP NOW — bookkeeping below runs under its shadow
                int base = v - Wn;
                ch = __ldg(&idx2[base]);
                t  = __ldg(&types[base]);
            }
        }

        // Ballot 1: queue spawned siblings (<=1/lane) by ballot-rank prefix
        unsigned S = __ballot_sync(FULL, spawn);
        if (spawn) {
            int p = tail + __popc(S & below);
            if (p < CAP) s_q[p] = make_int2(sv, __float_as_int(sc));
        }
        if (S) {
            tail = min(tail + __popc(S), CAP);
            __syncwarp();                        // spawn writes visible
        }

        // Ballot 2: idle lanes claim queued work; doubles as exit test
        unsigned idle = __ballot_sync(FULL, !active);
        int avail = tail - head;
        if (idle == FULL && avail == 0) break;   // nothing running, nothing queued
        if (avail > 0) {
            if (!active) {
                int rank = __popc(idle & below);
                if (rank < avail) {
                    int2 e = s_q[head + rank];
                    c = __int_as_float(e.y);
                    active = true;
                    int base = e.x - Wn;         // claimed node: issue its gather now
                    ch = __ldg(&idx2[base]);
                    t  = __ldg(&types[base]);
                }
            }
            int nidle = __popc(idle);
            head += (avail < nidle) ? avail : nidle;
        }
    }

    // Warp reduction
    #pragma unroll
    for (int s = 16; s > 0; s >>= 1)
        acc += __shfl_xor_sync(FULL, acc, s);

    if (lane == 0) {
        float root = acc * __ldg(w_term);
        out[0] = fmaf(root, __ldg(w_final), __ldg(b_final));
    }
}

extern "C" void kernel_launch(void* const* d_in, const int* in_sizes, int n_in,
                              void* d_out, int out_size) {
    const float* values     = (const float*)d_in[0];
    const int*   child_idx  = (const int*)d_in[1];   // [L-1, W, 2]
    const int*   node_types = (const int*)d_in[2];   // [L-1, W]
    const float* w_term     = (const float*)d_in[3];
    const float* w_plus     = (const float*)d_in[4];
    const float* w_minus    = (const float*)d_in[5];
    const float* w_final    = (const float*)d_in[6];
    const float* b_final    = (const float*)d_in[7];
    float* out = (float*)d_out;

    cone_kernel<<<1, 32>>>(values,
                           (const int2*)child_idx,
                           node_types,
                           w_term, w_plus, w_minus, w_final, b_final,
                           out);
}

// round 12
// speedup vs baseline: 1.0036x; 1.0036x over previous
#include <cuda_runtime.h>

#define Wn 262144
#define Ln 32
#define Nn (Ln * Wn)
#define CAP 2048   // spawned-sibling queue (nonterminals only); expected ~16 total

// Linear DAG cone evaluation, single warp.
// root = sum over path-tree leaves of (prod path weights) * values[leaf] * w_term.
// Active lanes follow one nonterminal child in registers; the address chain is
// branchless (SEL + predicated LDG). Terminal children fold into acc at fork;
// a second nonterminal child is queued via ballot prefix and claimed by idle lanes.
__global__ void __launch_bounds__(32) cone_kernel(
    const float* __restrict__ values,
    const int2*  __restrict__ idx2,     // child_idx as [L-1,W] int2
    const int*   __restrict__ types,    // node_types [L-1,W]
    const float* __restrict__ w_term,
    const float* __restrict__ w_plus,
    const float* __restrict__ w_minus,
    const float* __restrict__ w_final,
    const float* __restrict__ b_final,
    float* __restrict__ out)
{
    __shared__ int2 s_q[CAP];           // (node id, coef bits)

    const int lane = threadIdx.x;
    const unsigned below = (1u << lane) - 1u;
    const unsigned FULL = 0xFFFFFFFFu;
    const float2 P = *(const float2*)w_plus;
    const float2 M = *(const float2*)w_minus;

    float acc = 0.0f;
    int head = 0, tail = 0;             // warp-uniform cursors, no atomics

    bool  active = (lane == 0);
    int   v = Nn - 1;                   // root in lane 0's registers
    float c = 1.0f;

    for (int iter = 0; iter < 96; iter++) {
        bool spawn = false;
        int   sv = 0;
        float sc = 0.0f;

        if (active) {
            int base = v - Wn;                   // v guaranteed nonterminal
            int2 ch = __ldg(&idx2[base]);        // the dependent gather
            int  t  = __ldg(&types[base]);       // independent, overlapped

            // Branchless follow-selection on the address chain:
            bool xt = (ch.x < Wn), yt = (ch.y < Wn);
            v = xt ? ch.y : ch.x;                // follow x if nonterminal, else y

            float c0 = c * ((t == 1) ? P.x : M.x);
            float c1 = c * ((t == 1) ? P.y : M.y);

            if (xt) acc += c0 * __ldg(&values[ch.x]);   // terminal inline
            if (yt) acc += c1 * __ldg(&values[ch.y]);

            c = xt ? c1 : c0;                    // coef of the followed child
            spawn = (!xt) && (!yt);              // both nonterminal: queue y
            sv = ch.y; sc = c1;
            active = !(xt && yt);                // both terminal: lane done
        }

        // Ballot 1: queue spawned siblings (<=1/lane) by ballot-rank prefix
        unsigned S = __ballot_sync(FULL, spawn);
        if (spawn) {
            int p = tail + __popc(S & below);
            if (p < CAP) s_q[p] = make_int2(sv, __float_as_int(sc));
        }
        if (S) {
            tail = min(tail + __popc(S), CAP);
            __syncwarp();                        // spawn writes visible
        }

        // Ballot 2: idle lanes claim queued work; doubles as exit test
        unsigned idle = __ballot_sync(FULL, !active);
        int avail = tail - head;
        if (idle == FULL && avail == 0) break;   // nothing running, nothing queued
        if (avail > 0) {
            if (!active) {
                int rank = __popc(idle & below);
                if (rank < avail) {
                    int2 e = s_q[head + rank];
                    v = e.x;
                    c = __int_as_float(e.y);
                    active = true;
                }
            }
            int nidle = __popc(idle);
            head += (avail < nidle) ? avail : nidle;
        }
    }

    // Warp reduction
    #pragma unroll
    for (int s = 16; s > 0; s >>= 1)
        acc += __shfl_xor_sync(FULL, acc, s);

    if (lane == 0) {
        float root = acc * __ldg(w_term);
        out[0] = fmaf(root, __ldg(w_final), __ldg(b_final));
    }
}

extern "C" void kernel_launch(void* const* d_in, const int* in_sizes, int n_in,
                              void* d_out, int out_size) {
    const float* values     = (const float*)d_in[0];
    const int*   child_idx  = (const int*)d_in[1];   // [L-1, W, 2]
    const int*   node_types = (const int*)d_in[2];   // [L-1, W]
    const float* w_term     = (const float*)d_in[3];
    const float* w_plus     = (const float*)d_in[4];
    const float* w_minus    = (const float*)d_in[5];
    const float* w_final    = (const float*)d_in[6];
    const float* b_final    = (const float*)d_in[7];
    float* out = (float*)d_out;

    cone_kernel<<<1, 32>>>(values,
                           (const int2*)child_idx,
                           node_types,
                           w_term, w_plus, w_minus, w_final, b_final,
                           out);
}

// round 13
// speedup vs baseline: 1.0257x; 1.0221x over previous
#include <cuda_runtime.h>

#define Wn 262144
#define Ln 32
#define Nn (Ln * Wn)
#define CAP 512    // spawned-sibling queue; expected ~16 entries

// Linear DAG cone evaluation, warp-specialized:
//   warp 0 / lane 0: chases the primary root chain with zero warp bookkeeping
//   warp 1:          consumes spawned sibling subtrees from a smem queue
// root = sum over path-tree leaves of (prod path weights) * values[leaf] * w_term.
__global__ void __launch_bounds__(64) cone_kernel(
    const float* __restrict__ values,
    const int2*  __restrict__ idx2,     // child_idx as [L-1,W] int2
    const int*   __restrict__ types,    // node_types [L-1,W]
    const float* __restrict__ w_term,
    const float* __restrict__ w_plus,
    const float* __restrict__ w_minus,
    const float* __restrict__ w_final,
    const float* __restrict__ b_final,
    float* __restrict__ out)
{
    __shared__ int2 s_q[CAP];           // (node id, coef bits); 0 = not yet written
    __shared__ int  s_ptail;            // producer reservation counter
    __shared__ volatile int s_done;     // warp-0 chain finished
    __shared__ float s_part[2];

    const int tid  = threadIdx.x;
    const int wid  = tid >> 5;
    const int lane = tid & 31;
    const unsigned below = (1u << lane) - 1u;
    const unsigned FULL = 0xFFFFFFFFu;
    const float2 P = *(const float2*)w_plus;
    const float2 M = *(const float2*)w_minus;

    // Zero the queue (entries become valid when nonzero; node ids are >= Wn)
    for (int i = tid; i < CAP; i += 64) s_q[i] = make_int2(0, 0);
    if (tid == 0) { s_ptail = 0; s_done = 0; }
    __syncthreads();

    float acc = 0.0f;

    if (wid == 0) {
        // ---- Primary chain chaser: scalar loop, no ballots on the hop path
        if (lane == 0) {
            int v = Nn - 1;
            float c = 1.0f;
            for (int it = 0; it < 40; it++) {       // path length <= 31
                int base = v - Wn;
                int2 ch = __ldg(&idx2[base]);       // the dependent gather
                int  t  = __ldg(&types[base]);      // off the address chain
                float c0 = c * ((t == 1) ? P.x : M.x);
                float c1 = c * ((t == 1) ? P.y : M.y);
                bool xt = (ch.x < Wn), yt = (ch.y < Wn);
                if (xt) acc += c0 * __ldg(&values[ch.x]);
                if (yt) acc += c1 * __ldg(&values[ch.y]);
                if (!xt) {
                    if (!yt) {                      // spawn sibling subtree
                        int p = atomicAdd(&s_ptail, 1);
                        if (p < CAP) s_q[p] = make_int2(ch.y, __float_as_int(c1));
                    }
                    v = ch.x; c = c0;
                } else if (!yt) {
                    v = ch.y; c = c1;
                } else break;                       // both terminal: chain done
            }
            __threadfence_block();
            s_done = 1;
        }
    } else {
        // ---- Consumer warp: claim queued subtrees, follow them in registers
        int head = 0;
        bool active = false;
        int v = 0; float c = 0.0f;

        for (int it = 0; it < 4096; it++) {
            bool spawn = false; int sv = 0; float sc = 0.0f;

            if (active) {
                int base = v - Wn;
                int2 ch = __ldg(&idx2[base]);
                int  t  = __ldg(&types[base]);
                float c0 = c * ((t == 1) ? P.x : M.x);
                float c1 = c * ((t == 1) ? P.y : M.y);
                bool xt = (ch.x < Wn), yt = (ch.y < Wn);
                if (xt) acc += c0 * __ldg(&values[ch.x]);
                if (yt) acc += c1 * __ldg(&values[ch.y]);
                if (!xt) {
                    if (!yt) { spawn = true; sv = ch.y; sc = c1; }
                    v = ch.x; c = c0;
                } else if (!yt) {
                    v = ch.y; c = c1;
                } else active = false;
            }

            // Publish this warp's spawns (producer side, atomic reserve)
            if (spawn) {
                int p = atomicAdd(&s_ptail, 1);
                if (p < CAP) s_q[p] = make_int2(sv, __float_as_int(sc));
            }

            // Claim: read done BEFORE ptail (ptail only grows)
            int done = s_done;
            int pt = *(volatile int*)&s_ptail;
            if (pt > CAP) pt = CAP;                 // overflow slots never stored
            unsigned idle = __ballot_sync(FULL, !active);
            int avail = pt - head;
            if (!active) {
                int rank = __popc(idle & below);
                if (rank < avail) {
                    int slot = head + rank;
                    // spin until producer's 64-bit store lands (reserved => will land)
                    int nx;
                    do { nx = *(volatile int*)&s_q[slot].x; } while (nx == 0);
                    int cy = *(volatile int*)&s_q[slot].y;
                    v = nx; c = __int_as_float(cy);
                    active = true;
                }
            }
            int nidle = __popc(idle);
            head += (avail < nidle) ? avail : nidle;

            unsigned act = __ballot_sync(FULL, active);
            if (act == 0 && done && head >= pt) break;
        }
    }

    // Per-warp reduction, then combine
    #pragma unroll
    for (int s = 16; s > 0; s >>= 1)
        acc += __shfl_xor_sync(FULL, acc, s);
    if (lane == 0) s_part[wid] = acc;
    __syncthreads();

    if (tid == 0) {
        float root = (s_part[0] + s_part[1]) * __ldg(w_term);
        out[0] = fmaf(root, __ldg(w_final), __ldg(b_final));
    }
}

extern "C" void kernel_launch(void* const* d_in, const int* in_sizes, int n_in,
                              void* d_out, int out_size) {
    const float* values     = (const float*)d_in[0];
    const int*   child_idx  = (const int*)d_in[1];   // [L-1, W, 2]
    const int*   node_types = (const int*)d_in[2];   // [L-1, W]
    const float* w_term     = (const float*)d_in[3];
    const float* w_plus     = (const float*)d_in[4];
    const float* w_minus    = (const float*)d_in[5];
    const float* w_final    = (const float*)d_in[6];
    const float* b_final    = (const float*)d_in[7];
    float* out = (float*)d_out;

    cone_kernel<<<1, 64>>>(values,
                           (const int2*)child_idx,
                           node_types,
                           w_term, w_plus, w_minus, w_final, b_final,
                           out);
}